// round 2
// baseline (speedup 1.0000x reference)
#include <cuda_runtime.h>
#include <math.h>
#include <stdint.h>

// Problem constants
#define NB   2          // batch
#define NC   256        // channels
#define NS   1024       // spatial after pool (32*32)
#define NB2  4          // combined batch (2*NB)
#define RC   32         // reduced channels
#define KVK  768        // top-k
#define NJ   96         // 3*RC

// ---------------- scratch (device globals; no allocation allowed) ------------
__device__ float g_comb[NB2 * NC * NS];          // (b2, c, s) 4MB
__device__ float g_mean[NB2 * NC];
__device__ float g_gate[NB2];
__device__ float g_Wf[NJ * NC];                  // fused qkv weight
__device__ float g_bf[NJ];                       // fused qkv bias
__device__ float g_qkv[NB2 * NJ * NS];           // (b2, j, s) 1.5MB
__device__ float g_scores[(size_t)NB2 * NS * NS];// (b2, s, t) 16MB, becomes P
__device__ float g_attn[NB2 * NS * RC];          // (b2, s, r)

// ---------------- kernel A: 2x2 pool, mix, spatial means ---------------------
__global__ void k_pool_combine(const float* __restrict__ x,
                               const float* __restrict__ mix)
{
    int c = blockIdx.x;          // 0..255
    int b = blockIdx.y;          // 0..1
    int tid = threadIdx.x;       // 256
    const float* xp = x + ((size_t)(b * NC + c)) * 64 * 64;
    float mw = 1.f / (1.f + __expf(-mix[0]));
    float* o1 = g_comb + ((size_t)((2 * b) * NC + c)) * NS;
    float* o2 = g_comb + ((size_t)((2 * b + 1) * NC + c)) * NS;
    float s1 = 0.f, s2 = 0.f;
    #pragma unroll
    for (int p = tid; p < NS; p += 256) {
        int i = p >> 5, j = p & 31;
        const float* r0 = xp + (2 * i) * 64 + 2 * j;
        float a = r0[0], bb = r0[1], cc = r0[64], dd = r0[65];
        float mx = fmaxf(fmaxf(a, bb), fmaxf(cc, dd));
        float av = (a + bb + cc + dd) * 0.25f;
        float x1 = mx + mw * (av - mx);
        float x2 = av + mw * (mx - av);
        o1[p] = x1; o2[p] = x2;
        s1 += x1; s2 += x2;
    }
    __shared__ float sh0[256], sh1[256];
    sh0[tid] = s1; sh1[tid] = s2;
    __syncthreads();
    for (int st = 128; st > 0; st >>= 1) {
        if (tid < st) { sh0[tid] += sh0[tid + st]; sh1[tid] += sh1[tid + st]; }
        __syncthreads();
    }
    if (tid == 0) {
        g_mean[(2 * b) * NC + c]     = sh0[0] * (1.f / (float)NS);
        g_mean[(2 * b + 1) * NC + c] = sh1[0] * (1.f / (float)NS);
    }
}

// ---------------- kernel W: fold w_red into w_qkv ----------------------------
__global__ void k_fuse_w(const float* __restrict__ w_red,
                         const float* __restrict__ b_red,
                         const float* __restrict__ w_qkv,
                         const float* __restrict__ b_qkv)
{
    int j = blockIdx.x;      // 0..95
    int c = threadIdx.x;     // 0..255
    float acc = 0.f;
    #pragma unroll
    for (int r = 0; r < RC; r++)
        acc += w_qkv[j * RC + r] * w_red[r * NC + c];
    g_Wf[j * NC + c] = acc;
    if (c == 0) {
        float bb = b_qkv[j];
        #pragma unroll
        for (int r = 0; r < RC; r++) bb += w_qkv[j * RC + r] * b_red[r];
        g_bf[j] = bb;
    }
}

// ---------------- kernel B: gating MLP ---------------------------------------
__global__ void k_gating(const float* __restrict__ w_s1,
                         const float* __restrict__ b_s1,
                         const float* __restrict__ w_s2,
                         const float* __restrict__ b_s2)
{
    int u = threadIdx.x;     // 128
    __shared__ float sh[128];
    for (int b2 = 0; b2 < NB2; b2++) {
        float acc = b_s1[u];
        const float* row = w_s1 + (size_t)u * NC;
        const float* pm  = g_mean + b2 * NC;
        #pragma unroll 8
        for (int c = 0; c < NC; c++) acc += row[c] * pm[c];
        float h = fmaxf(acc, 0.f);
        sh[u] = h * w_s2[u];
        __syncthreads();
        for (int st = 64; st > 0; st >>= 1) {
            if (u < st) sh[u] += sh[u + st];
            __syncthreads();
        }
        if (u == 0) {
            float z = sh[0] + b_s2[0];
            g_gate[b2] = (z > 0.f) ? 1.f : 0.f;   // sigmoid(z) > 0.5
        }
        __syncthreads();
    }
}

// ---------------- kernel C: gated max -> first output part -------------------
__global__ void k_gate_max(float* __restrict__ dst)
{
    int idx = blockIdx.x * 256 + threadIdx.x;     // 2*256*1024 total
    int b  = idx >> 18;
    int cs = idx & 262143;
    float g0 = g_gate[2 * b], g1 = g_gate[2 * b + 1];
    float v0 = g_comb[(size_t)(2 * b) * NC * NS + cs] * g0;
    float v1 = g_comb[(size_t)(2 * b + 1) * NC * NS + cs] * g1;
    dst[idx] = fmaxf(v0, v1);
}

// ---------------- kernel QKV: qkv(b2,j,s) = Wf @ comb + bf -------------------
__global__ void k_qkv(void)
{
    int b2 = blockIdx.y;
    int s0 = blockIdx.x * 32;
    __shared__ float As[64][33];      // [c_local][s_local]
    __shared__ float Ws[NJ][64];      // [j][c_local]
    int tid = threadIdx.x;            // 256
    int sl = tid & 31, jg = tid >> 5; // jg 0..7 handles j = jg*12..+12
    float acc[12];
    #pragma unroll
    for (int i = 0; i < 12; i++) acc[i] = 0.f;
    for (int c0 = 0; c0 < NC; c0 += 64) {
        for (int idx = tid; idx < 2048; idx += 256) {
            int cc = idx >> 5, ss = idx & 31;
            As[cc][ss] = g_comb[(size_t)(b2 * NC + c0 + cc) * NS + s0 + ss];
        }
        for (int idx = tid; idx < NJ * 64; idx += 256) {
            int j = idx >> 6, cc = idx & 63;
            Ws[j][cc] = g_Wf[j * NC + c0 + cc];
        }
        __syncthreads();
        #pragma unroll 4
        for (int cc = 0; cc < 64; cc++) {
            float a = As[cc][sl];
            #pragma unroll
            for (int jj = 0; jj < 12; jj++)
                acc[jj] += a * Ws[jg * 12 + jj][cc];
        }
        __syncthreads();
    }
    #pragma unroll
    for (int jj = 0; jj < 12; jj++) {
        int j = jg * 12 + jj;
        g_qkv[(size_t)(b2 * NJ + j) * NS + s0 + sl] = acc[jj] + g_bf[j];
    }
}

// ---------------- kernel D1: scores = q @ k^T / sqrt(rc) ---------------------
__global__ void k_scores(void)
{
    int b2 = blockIdx.z;
    int s0 = blockIdx.y * 64;
    int t0 = blockIdx.x * 64;
    __shared__ __align__(16) float Qs[RC][64];
    __shared__ __align__(16) float Ks[RC][64];
    int tid = threadIdx.x;                 // 256
    const float* qb = g_qkv + (size_t)(b2 * NJ) * NS;       // j 0..31
    const float* kb = qb + (size_t)RC * NS;                 // j 32..63
    for (int idx = tid; idx < RC * 64; idx += 256) {
        int j = idx >> 6, cc = idx & 63;
        Qs[j][cc] = qb[(size_t)j * NS + s0 + cc];
        Ks[j][cc] = kb[(size_t)j * NS + t0 + cc];
    }
    __syncthreads();
    int tx = tid & 15, ty = tid >> 4;      // 4 t x 4 s per thread
    float a00=0,a01=0,a02=0,a03=0, a10=0,a11=0,a12=0,a13=0;
    float a20=0,a21=0,a22=0,a23=0, a30=0,a31=0,a32=0,a33=0;
    #pragma unroll
    for (int k = 0; k < RC; k++) {
        float4 a = *(const float4*)&Qs[k][ty * 4];
        float4 b = *(const float4*)&Ks[k][tx * 4];
        a00+=a.x*b.x; a01+=a.x*b.y; a02+=a.x*b.z; a03+=a.x*b.w;
        a10+=a.y*b.x; a11+=a.y*b.y; a12+=a.y*b.z; a13+=a.y*b.w;
        a20+=a.z*b.x; a21+=a.z*b.y; a22+=a.z*b.z; a23+=a.z*b.w;
        a30+=a.w*b.x; a31+=a.w*b.y; a32+=a.w*b.z; a33+=a.w*b.w;
    }
    const float sc = 0.17677669529663687f;  // 1/sqrt(32)
    size_t base = ((size_t)b2 * NS) * NS;
    float4 o;
    o.x=a00*sc; o.y=a01*sc; o.z=a02*sc; o.w=a03*sc;
    *(float4*)&g_scores[base + (size_t)(s0 + ty*4 + 0) * NS + t0 + tx*4] = o;
    o.x=a10*sc; o.y=a11*sc; o.z=a12*sc; o.w=a13*sc;
    *(float4*)&g_scores[base + (size_t)(s0 + ty*4 + 1) * NS + t0 + tx*4] = o;
    o.x=a20*sc; o.y=a21*sc; o.z=a22*sc; o.w=a23*sc;
    *(float4*)&g_scores[base + (size_t)(s0 + ty*4 + 2) * NS + t0 + tx*4] = o;
    o.x=a30*sc; o.y=a31*sc; o.z=a32*sc; o.w=a33*sc;
    *(float4*)&g_scores[base + (size_t)(s0 + ty*4 + 3) * NS + t0 + tx*4] = o;
}

// ---------------- kernel D2: exact top-768 + masked softmax (in place) -------
// warp per row; keys are monotonic uint transforms of the scores.
__global__ void k_topk_softmax(void)
{
    int warp = (blockIdx.x * blockDim.x + threadIdx.x) >> 5;   // 0..4095
    int lane = threadIdx.x & 31;
    float* sp = g_scores + (size_t)warp * NS;

    unsigned key[32];
    float vmax = -INFINITY;
    #pragma unroll
    for (int i = 0; i < 32; i++) {
        float f = sp[i * 32 + lane];
        unsigned u = __float_as_uint(f);
        key[i] = (u & 0x80000000u) ? ~u : (u | 0x80000000u);
        vmax = fmaxf(vmax, f);
    }
    #pragma unroll
    for (int o = 16; o; o >>= 1) vmax = fmaxf(vmax, __shfl_xor_sync(~0u, vmax, o));

    // radix select: find the 768th-largest key exactly
    unsigned act = 0xFFFFFFFFu;
    unsigned prefix = 0;
    int remaining = KVK;
    for (int bit = 31; bit >= 0; --bit) {
        unsigned bmask = 1u << bit;
        unsigned bset = 0;
        unsigned m = act;
        while (m) {
            int i = __ffs(m) - 1; m &= m - 1;
            if (key[i] & bmask) bset |= (1u << i);
        }
        int cnt = __popc(bset);
        #pragma unroll
        for (int o = 16; o; o >>= 1) cnt += __shfl_xor_sync(~0u, cnt, o);
        if (cnt >= remaining) { act = bset; prefix |= bmask; }
        else                  { act &= ~bset; remaining -= cnt; }
    }
    unsigned Tk = prefix;
    int need = remaining;          // # ties at Tk to take (lowest index first)

    // pass 1: selection mask + Z
    unsigned selmask = 0;
    float Zl = 0.f;
    int taken = 0;
    unsigned lmask = (1u << lane) - 1u;
    #pragma unroll
    for (int i = 0; i < 32; i++) {
        bool gt = key[i] > Tk;
        bool eq = key[i] == Tk;
        unsigned bal = __ballot_sync(~0u, eq);
        int rank = taken + __popc(bal & lmask);
        taken += __popc(bal);
        bool sel = gt || (eq && rank < need);
        if (sel) {
            selmask |= (1u << i);
            unsigned kk = key[i];
            unsigned u = (kk & 0x80000000u) ? (kk & 0x7FFFFFFFu) : ~kk;
            Zl += __expf(__uint_as_float(u) - vmax);
        }
    }
    #pragma unroll
    for (int o = 16; o; o >>= 1) Zl += __shfl_xor_sync(~0u, Zl, o);
    float inv = 1.f / Zl;

    // pass 2: write probabilities
    #pragma unroll
    for (int i = 0; i < 32; i++) {
        float p = 0.f;
        if (selmask & (1u << i)) {
            unsigned kk = key[i];
            unsigned u = (kk & 0x80000000u) ? (kk & 0x7FFFFFFFu) : ~kk;
            p = __expf(__uint_as_float(u) - vmax) * inv;
        }
        sp[i * 32 + lane] = p;
    }
}

// ---------------- kernel D3: attn = P @ V ------------------------------------
__global__ void k_attn_av(void)
{
    int b2 = blockIdx.y;
    int s0 = blockIdx.x * 32;
    __shared__ __align__(16) float Ps[32][65];
    __shared__ __align__(16) float Vs[64][36];   // [t][r], 144B rows (16B aligned)
    int tid = threadIdx.x;              // 256
    int r4 = (tid & 7) * 4;             // 4 consecutive r per thread
    int sl = tid >> 3;                  // 0..31
    float a0 = 0.f, a1 = 0.f, a2 = 0.f, a3 = 0.f;
    const float* vbase = g_qkv + (size_t)(b2 * NJ + 64) * NS;
    const float* pbase = g_scores + ((size_t)(b2 * NS + s0)) * NS;
    for (int tt = 0; tt < NS; tt += 64) {
        for (int idx = tid; idx < 2048; idx += 256) {
            int sr = idx >> 6, tc = idx & 63;
            Ps[sr][tc] = pbase[(size_t)sr * NS + tt + tc];
        }
        for (int idx = tid; idx < 2048; idx += 256) {
            int r = idx >> 6, tc = idx & 63;
            Vs[tc][r] = vbase[(size_t)r * NS + tt + tc];
        }
        __syncthreads();
        #pragma unroll 8
        for (int t = 0; t < 64; t++) {
            float p = Ps[sl][t];
            float4 v = *(const float4*)&Vs[t][r4];
            a0 += p * v.x; a1 += p * v.y; a2 += p * v.z; a3 += p * v.w;
        }
        __syncthreads();
    }
    float4 o; o.x = a0; o.y = a1; o.z = a2; o.w = a3;
    *(float4*)&g_attn[(size_t)(b2 * NS + s0 + sl) * RC + r4] = o;
}

// ---------------- kernel E: project back through w_red -----------------------
__global__ void k_attn_proj(const float* __restrict__ w_red,
                            float* __restrict__ dst)
{
    int b2 = blockIdx.z;
    int s0 = blockIdx.x * 128;
    int c0 = blockIdx.y * 32;
    __shared__ __align__(16) float Os[128][33];   // [s][r]
    __shared__ __align__(16) float Ws[RC][32];    // [r][c]
    int tid = threadIdx.x;   // 256
    for (int idx = tid; idx < 128 * RC; idx += 256) {
        int sr = idx >> 5, r = idx & 31;
        Os[sr][r] = g_attn[(size_t)(b2 * NS + s0 + sr) * RC + r];
    }
    for (int idx = tid; idx < RC * 32; idx += 256) {
        int r = idx >> 5, cc = idx & 31;
        Ws[r][cc] = w_red[r * NC + c0 + cc];
    }
    __syncthreads();
    int sl = tid & 127;
    int cg = (tid >> 7) * 16;
    float4 acc0 = {0,0,0,0}, acc1 = {0,0,0,0}, acc2 = {0,0,0,0}, acc3 = {0,0,0,0};
    #pragma unroll
    for (int r = 0; r < RC; r++) {
        float o = Os[sl][r];
        float4 w0 = *(const float4*)&Ws[r][cg + 0];
        float4 w1 = *(const float4*)&Ws[r][cg + 4];
        float4 w2 = *(const float4*)&Ws[r][cg + 8];
        float4 w3 = *(const float4*)&Ws[r][cg + 12];
        acc0.x += o*w0.x; acc0.y += o*w0.y; acc0.z += o*w0.z; acc0.w += o*w0.w;
        acc1.x += o*w1.x; acc1.y += o*w1.y; acc1.z += o*w1.z; acc1.w += o*w1.w;
        acc2.x += o*w2.x; acc2.y += o*w2.y; acc2.z += o*w2.z; acc2.w += o*w2.w;
        acc3.x += o*w3.x; acc3.y += o*w3.y; acc3.z += o*w3.z; acc3.w += o*w3.w;
    }
    float accs[16] = {acc0.x,acc0.y,acc0.z,acc0.w, acc1.x,acc1.y,acc1.z,acc1.w,
                      acc2.x,acc2.y,acc2.z,acc2.w, acc3.x,acc3.y,acc3.z,acc3.w};
    #pragma unroll
    for (int i = 0; i < 16; i++)
        dst[(size_t)(b2 * NC + c0 + cg + i) * NS + s0 + sl] = accs[i];
}

// ---------------- launcher ---------------------------------------------------
extern "C" void kernel_launch(void* const* d_in, const int* in_sizes, int n_in,
                              void* d_out, int out_size)
{
    const float* x        = (const float*)d_in[0];
    const float* mix      = (const float*)d_in[1];
    const float* w_red    = (const float*)d_in[2];
    const float* b_red    = (const float*)d_in[3];
    const float* w_qkv    = (const float*)d_in[4];
    const float* b_qkv    = (const float*)d_in[5];
    const float* w_s1     = (const float*)d_in[6];
    const float* b_s1     = (const float*)d_in[7];
    const float* w_s2     = (const float*)d_in[8];
    const float* b_s2     = (const float*)d_in[9];
    float* out = (float*)d_out;
    float* out_attn = out + (size_t)NB * NC * NS;   // 524288 offset

    k_pool_combine<<<dim3(NC, NB), 256>>>(x, mix);
    k_fuse_w<<<NJ, 256>>>(w_red, b_red, w_qkv, b_qkv);
    k_gating<<<1, 128>>>(w_s1, b_s1, w_s2, b_s2);
    k_gate_max<<<(NB * NC * NS) / 256, 256>>>(out);
    k_qkv<<<dim3(NS / 32, NB2), 256>>>();
    k_scores<<<dim3(NS / 64, NS / 64, NB2), 256>>>();
    k_topk_softmax<<<(NB2 * NS) / 8, 256>>>();
    k_attn_av<<<dim3(NS / 32, NB2), 256>>>();
    k_attn_proj<<<dim3(NS / 128, NC / 32, NB2), 256>>>(w_red, out_attn);
}

// round 8
// speedup vs baseline: 1.2664x; 1.2664x over previous
#include <cuda_runtime.h>
#include <math.h>
#include <stdint.h>

// Problem constants
#define NB   2          // batch
#define NC   256        // channels
#define NS   1024       // spatial after pool (32*32)
#define NB2  4          // combined batch (2*NB)
#define RC   32         // reduced channels
#define KVK  768        // top-k
#define NJ   96         // 3*RC

// ---------------- scratch (device globals; no allocation allowed) ------------
__device__ float g_comb[NB2 * NC * NS];          // (b2, c, s) 4MB
__device__ float g_mean[NB2 * NC];
__device__ float g_gate[NB2];
__device__ float g_Wf[NJ * NC];                  // fused qkv weight
__device__ float g_bf[NJ];                       // fused qkv bias
__device__ float g_qkv[NB2 * NJ * NS];           // (b2, j, s) 1.5MB
__device__ float g_scores[(size_t)NB2 * NS * NS];// (b2, s, t) 16MB, becomes P
__device__ float g_vt[NB2 * NS * RC];            // V transposed: (b2, t, r)
__device__ float g_attn_part[4][NB2 * NS * RC];  // t-chunk partials
__device__ float g_attn[NB2 * NS * RC];          // (b2, s, r)

// ---------------- kernel A: 2x2 pool, mix, spatial means ---------------------
__global__ void k_pool_combine(const float* __restrict__ x,
                               const float* __restrict__ mix)
{
    int c = blockIdx.x;          // 0..255
    int b = blockIdx.y;          // 0..1
    int tid = threadIdx.x;       // 256
    const float* xp = x + ((size_t)(b * NC + c)) * 64 * 64;
    float mw = 1.f / (1.f + __expf(-mix[0]));
    float* o1 = g_comb + ((size_t)((2 * b) * NC + c)) * NS;
    float* o2 = g_comb + ((size_t)((2 * b + 1) * NC + c)) * NS;
    float s1 = 0.f, s2 = 0.f;
    #pragma unroll
    for (int p = tid; p < NS; p += 256) {
        int i = p >> 5, j = p & 31;
        const float* r0 = xp + (2 * i) * 64 + 2 * j;
        float2 t0 = *(const float2*)&r0[0];
        float2 t1 = *(const float2*)&r0[64];
        float a = t0.x, bb = t0.y, cc = t1.x, dd = t1.y;
        float mx = fmaxf(fmaxf(a, bb), fmaxf(cc, dd));
        float av = (a + bb + cc + dd) * 0.25f;
        float x1 = mx + mw * (av - mx);
        float x2 = av + mw * (mx - av);
        o1[p] = x1; o2[p] = x2;
        s1 += x1; s2 += x2;
    }
    __shared__ float sh0[256], sh1[256];
    sh0[tid] = s1; sh1[tid] = s2;
    __syncthreads();
    for (int st = 128; st > 0; st >>= 1) {
        if (tid < st) { sh0[tid] += sh0[tid + st]; sh1[tid] += sh1[tid + st]; }
        __syncthreads();
    }
    if (tid == 0) {
        g_mean[(2 * b) * NC + c]     = sh0[0] * (1.f / (float)NS);
        g_mean[(2 * b + 1) * NC + c] = sh1[0] * (1.f / (float)NS);
    }
}

// ---------------- kernel W: fold w_red into w_qkv ----------------------------
__global__ void k_fuse_w(const float* __restrict__ w_red,
                         const float* __restrict__ b_red,
                         const float* __restrict__ w_qkv,
                         const float* __restrict__ b_qkv)
{
    int j = blockIdx.x;      // 0..95
    int c = threadIdx.x;     // 0..255
    float acc = 0.f;
    #pragma unroll
    for (int r = 0; r < RC; r++)
        acc += w_qkv[j * RC + r] * w_red[r * NC + c];
    g_Wf[j * NC + c] = acc;
    if (c == 0) {
        float bb = b_qkv[j];
        #pragma unroll
        for (int r = 0; r < RC; r++) bb += w_qkv[j * RC + r] * b_red[r];
        g_bf[j] = bb;
    }
}

// ---------------- kernel B: gating MLP ---------------------------------------
__global__ void k_gating(const float* __restrict__ w_s1,
                         const float* __restrict__ b_s1,
                         const float* __restrict__ w_s2,
                         const float* __restrict__ b_s2)
{
    int u = threadIdx.x;     // 128
    __shared__ float sh[128];
    for (int b2 = 0; b2 < NB2; b2++) {
        float acc = b_s1[u];
        const float* row = w_s1 + (size_t)u * NC;
        const float* pm  = g_mean + b2 * NC;
        #pragma unroll 8
        for (int c = 0; c < NC; c++) acc += row[c] * pm[c];
        float h = fmaxf(acc, 0.f);
        sh[u] = h * w_s2[u];
        __syncthreads();
        for (int st = 64; st > 0; st >>= 1) {
            if (u < st) sh[u] += sh[u + st];
            __syncthreads();
        }
        if (u == 0) {
            float z = sh[0] + b_s2[0];
            g_gate[b2] = (z > 0.f) ? 1.f : 0.f;   // sigmoid(z) > 0.5
        }
        __syncthreads();
    }
}

// ---------------- kernel C: gated max -> first output part (float4) ----------
__global__ void k_gate_max(float* __restrict__ dst)
{
    int i = blockIdx.x * 256 + threadIdx.x;       // 131072 float4 total
    int b  = i >> 16;                             // 65536 float4 per batch
    int cs = i & 65535;
    float g0 = g_gate[2 * b], g1 = g_gate[2 * b + 1];
    const float4* p0 = (const float4*)g_comb + (size_t)(2 * b) * 65536 + cs;
    const float4* p1 = (const float4*)g_comb + (size_t)(2 * b + 1) * 65536 + cs;
    float4 v0 = *p0, v1 = *p1, o;
    o.x = fmaxf(v0.x * g0, v1.x * g1);
    o.y = fmaxf(v0.y * g0, v1.y * g1);
    o.z = fmaxf(v0.z * g0, v1.z * g1);
    o.w = fmaxf(v0.w * g0, v1.w * g1);
    ((float4*)dst)[i] = o;
}

// ---------------- kernel QKV v2: tiled GEMM qkv = Wf @ comb + bf -------------
__global__ void k_qkv(void)
{
    int b2 = blockIdx.z;
    int j0 = blockIdx.y * 32;
    int s0 = blockIdx.x * 64;
    __shared__ __align__(16) float As[32][68];   // [k][s]
    __shared__ float Ws[32][33];                 // [k][j]
    int tid = threadIdx.x;           // 256
    int tx = tid & 15, ty = tid >> 4;
    int s4 = tx * 4, j2 = ty * 2;
    float a00=0,a01=0,a02=0,a03=0, a10=0,a11=0,a12=0,a13=0;
    for (int c0 = 0; c0 < NC; c0 += 32) {
        #pragma unroll
        for (int idx = tid; idx < 2048; idx += 256) {
            int kk = idx >> 6, ss = idx & 63;
            As[kk][ss] = g_comb[(size_t)(b2 * NC + c0 + kk) * NS + s0 + ss];
        }
        #pragma unroll
        for (int idx = tid; idx < 1024; idx += 256) {
            int j = idx >> 5, kk = idx & 31;
            Ws[kk][j] = g_Wf[(j0 + j) * NC + c0 + kk];
        }
        __syncthreads();
        #pragma unroll
        for (int kk = 0; kk < 32; kk++) {
            float4 a = *(const float4*)&As[kk][s4];
            float w0 = Ws[kk][j2], w1 = Ws[kk][j2 + 1];
            a00 += w0*a.x; a01 += w0*a.y; a02 += w0*a.z; a03 += w0*a.w;
            a10 += w1*a.x; a11 += w1*a.y; a12 += w1*a.z; a13 += w1*a.w;
        }
        __syncthreads();
    }
    float bb0 = g_bf[j0 + j2], bb1 = g_bf[j0 + j2 + 1];
    float4 o0; o0.x=a00+bb0; o0.y=a01+bb0; o0.z=a02+bb0; o0.w=a03+bb0;
    float4 o1; o1.x=a10+bb1; o1.y=a11+bb1; o1.z=a12+bb1; o1.w=a13+bb1;
    *(float4*)&g_qkv[(size_t)(b2 * NJ + j0 + j2    ) * NS + s0 + s4] = o0;
    *(float4*)&g_qkv[(size_t)(b2 * NJ + j0 + j2 + 1) * NS + s0 + s4] = o1;
}

// ---------------- kernel D1: scores = q @ k^T / sqrt(rc) ---------------------
__global__ void k_scores(void)
{
    int b2 = blockIdx.z;
    int s0 = blockIdx.y * 64;
    int t0 = blockIdx.x * 64;
    __shared__ __align__(16) float Qs[RC][64];
    __shared__ __align__(16) float Ks[RC][64];
    int tid = threadIdx.x;                 // 256
    const float* qb = g_qkv + (size_t)(b2 * NJ) * NS;       // j 0..31
    const float* kb = qb + (size_t)RC * NS;                 // j 32..63
    #pragma unroll
    for (int idx = tid; idx < RC * 64; idx += 256) {
        int j = idx >> 6, cc = idx & 63;
        Qs[j][cc] = qb[(size_t)j * NS + s0 + cc];
        Ks[j][cc] = kb[(size_t)j * NS + t0 + cc];
    }
    __syncthreads();
    int tx = tid & 15, ty = tid >> 4;      // 4 t x 4 s per thread
    float a00=0,a01=0,a02=0,a03=0, a10=0,a11=0,a12=0,a13=0;
    float a20=0,a21=0,a22=0,a23=0, a30=0,a31=0,a32=0,a33=0;
    #pragma unroll
    for (int k = 0; k < RC; k++) {
        float4 a = *(const float4*)&Qs[k][ty * 4];
        float4 b = *(const float4*)&Ks[k][tx * 4];
        a00+=a.x*b.x; a01+=a.x*b.y; a02+=a.x*b.z; a03+=a.x*b.w;
        a10+=a.y*b.x; a11+=a.y*b.y; a12+=a.y*b.z; a13+=a.y*b.w;
        a20+=a.z*b.x; a21+=a.z*b.y; a22+=a.z*b.z; a23+=a.z*b.w;
        a30+=a.w*b.x; a31+=a.w*b.y; a32+=a.w*b.z; a33+=a.w*b.w;
    }
    const float sc = 0.17677669529663687f;  // 1/sqrt(32)
    size_t base = ((size_t)b2 * NS) * NS;
    float4 o;
    o.x=a00*sc; o.y=a01*sc; o.z=a02*sc; o.w=a03*sc;
    *(float4*)&g_scores[base + (size_t)(s0 + ty*4 + 0) * NS + t0 + tx*4] = o;
    o.x=a10*sc; o.y=a11*sc; o.z=a12*sc; o.w=a13*sc;
    *(float4*)&g_scores[base + (size_t)(s0 + ty*4 + 1) * NS + t0 + tx*4] = o;
    o.x=a20*sc; o.y=a21*sc; o.z=a22*sc; o.w=a23*sc;
    *(float4*)&g_scores[base + (size_t)(s0 + ty*4 + 2) * NS + t0 + tx*4] = o;
    o.x=a30*sc; o.y=a31*sc; o.z=a32*sc; o.w=a33*sc;
    *(float4*)&g_scores[base + (size_t)(s0 + ty*4 + 3) * NS + t0 + tx*4] = o;
}

// ---------------- kernel VT: transpose V to (t, r) ---------------------------
__global__ void k_vtrans(void)
{
    int b2 = blockIdx.y;
    int t0 = blockIdx.x * 64;
    __shared__ float tile[64][33];
    int tid = threadIdx.x;     // 256
    const float* vbase = g_qkv + (size_t)(b2 * NJ + 64) * NS;
    #pragma unroll
    for (int idx = tid; idx < 2048; idx += 256) {
        int r = idx >> 6, t = idx & 63;
        tile[t][r] = vbase[(size_t)r * NS + t0 + t];
    }
    __syncthreads();
    #pragma unroll
    for (int idx = tid; idx < 2048; idx += 256) {
        int t = idx >> 5, r = idx & 31;
        g_vt[(size_t)(b2 * NS + t0 + t) * RC + r] = tile[t][r];
    }
}

// ---------------- kernel D2: exact top-768 + masked softmax (in place) -------
// warp per row. Static-indexed radix binary search + REDUX; no local memory.
__global__ void k_topk_softmax(void)
{
    int warp = (blockIdx.x * blockDim.x + threadIdx.x) >> 5;   // 0..4095
    int lane = threadIdx.x & 31;
    float* sp = g_scores + (size_t)warp * NS;

    unsigned key[32];
    float vmax = -INFINITY;
    #pragma unroll
    for (int i = 0; i < 32; i++) {
        float f = sp[i * 32 + lane];
        unsigned u = __float_as_uint(f);
        key[i] = (u & 0x80000000u) ? ~u : (u | 0x80000000u);
        vmax = fmaxf(vmax, f);
    }
    #pragma unroll
    for (int o = 16; o; o >>= 1) vmax = fmaxf(vmax, __shfl_xor_sync(~0u, vmax, o));

    // bit-serial binary search for the exact 768th-largest key
    unsigned prefix = 0;
    int remaining = KVK;
    #pragma unroll
    for (int bit = 31; bit >= 0; --bit) {
        unsigned want = prefix | (1u << bit);
        int cnt = 0;
        #pragma unroll
        for (int i = 0; i < 32; i++)
            cnt += (int)(((key[i] ^ want) >> bit) == 0u);
        cnt = __reduce_add_sync(0xFFFFFFFFu, cnt);
        if (cnt >= remaining) prefix = want;
        else                  remaining -= cnt;
    }
    unsigned Tk = prefix;
    int need = remaining;          // # ties at Tk to take (lowest index first)

    // pass 1: selection mask + Z
    unsigned selmask = 0;
    float Zl = 0.f;
    int taken = 0;
    unsigned lmask = (1u << lane) - 1u;
    #pragma unroll
    for (int i = 0; i < 32; i++) {
        bool gt = key[i] > Tk;
        bool eq = key[i] == Tk;
        unsigned bal = __ballot_sync(~0u, eq);
        int rank = taken + __popc(bal & lmask);
        taken += __popc(bal);
        bool sel = gt || (eq && rank < need);
        if (sel) {
            selmask |= (1u << i);
            unsigned kk = key[i];
            unsigned u = (kk & 0x80000000u) ? (kk & 0x7FFFFFFFu) : ~kk;
            Zl += __expf(__uint_as_float(u) - vmax);
        }
    }
    #pragma unroll
    for (int o = 16; o; o >>= 1) Zl += __shfl_xor_sync(~0u, Zl, o);
    float inv = 1.f / Zl;

    // pass 2: write probabilities
    #pragma unroll
    for (int i = 0; i < 32; i++) {
        float p = 0.f;
        if (selmask & (1u << i)) {
            unsigned kk = key[i];
            unsigned u = (kk & 0x80000000u) ? (kk & 0x7FFFFFFFu) : ~kk;
            p = __expf(__uint_as_float(u) - vmax) * inv;
        }
        sp[i * 32 + lane] = p;
    }
}

// ---------------- kernel D3: attn partials = P @ V (t-chunked) ---------------
__global__ void k_attn_av(void)
{
    int b2 = blockIdx.z;
    int tc = blockIdx.y;             // 0..3 (t chunk of 256)
    int s0 = blockIdx.x * 64;        // 16 s tiles
    int tid = threadIdx.x;           // 128
    int tx = tid & 15, ty = tid >> 4;    // tx->s, ty->r (0..7)
    int s4 = tx * 4, r4 = ty * 4;
    __shared__ float Ps[64][65];                 // [s][t]
    __shared__ __align__(16) float Vs[64][32];   // [t][r] flat-contiguous
    float a00=0,a01=0,a02=0,a03=0, a10=0,a11=0,a12=0,a13=0;
    float a20=0,a21=0,a22=0,a23=0, a30=0,a31=0,a32=0,a33=0;
    const float* pbase = g_scores + ((size_t)(b2 * NS + s0)) * NS;
    const float* vt = g_vt + (size_t)b2 * NS * RC;
    for (int tt = tc * 256; tt < tc * 256 + 256; tt += 64) {
        #pragma unroll
        for (int idx = tid; idx < 4096; idx += 128) {
            int sr = idx >> 6, tl = idx & 63;
            Ps[sr][tl] = pbase[(size_t)sr * NS + tt + tl];
        }
        {
            const float4* src = (const float4*)&vt[(size_t)tt * RC];
            float4* dst = (float4*)&Vs[0][0];
            #pragma unroll
            for (int i = tid; i < 512; i += 128) dst[i] = src[i];
        }
        __syncthreads();
        #pragma unroll 8
        for (int t = 0; t < 64; t++) {
            float4 v = *(const float4*)&Vs[t][r4];
            float p0 = Ps[s4 + 0][t], p1 = Ps[s4 + 1][t];
            float p2 = Ps[s4 + 2][t], p3 = Ps[s4 + 3][t];
            a00 += p0*v.x; a01 += p0*v.y; a02 += p0*v.z; a03 += p0*v.w;
            a10 += p1*v.x; a11 += p1*v.y; a12 += p1*v.z; a13 += p1*v.w;
            a20 += p2*v.x; a21 += p2*v.y; a22 += p2*v.z; a23 += p2*v.w;
            a30 += p3*v.x; a31 += p3*v.y; a32 += p3*v.z; a33 += p3*v.w;
        }
        __syncthreads();
    }
    float* pp = g_attn_part[tc];
    float4 o;
    o.x=a00; o.y=a01; o.z=a02; o.w=a03;
    *(float4*)&pp[(size_t)(b2 * NS + s0 + s4 + 0) * RC + r4] = o;
    o.x=a10; o.y=a11; o.z=a12; o.w=a13;
    *(float4*)&pp[(size_t)(b2 * NS + s0 + s4 + 1) * RC + r4] = o;
    o.x=a20; o.y=a21; o.z=a22; o.w=a23;
    *(float4*)&pp[(size_t)(b2 * NS + s0 + s4 + 2) * RC + r4] = o;
    o.x=a30; o.y=a31; o.z=a32; o.w=a33;
    *(float4*)&pp[(size_t)(b2 * NS + s0 + s4 + 3) * RC + r4] = o;
}

// ---------------- kernel D4: deterministic partial reduce --------------------
__global__ void k_attn_reduce(void)
{
    int i = blockIdx.x * 256 + threadIdx.x;   // 32768 float4
    float4 a = ((const float4*)g_attn_part[0])[i];
    float4 b = ((const float4*)g_attn_part[1])[i];
    float4 c = ((const float4*)g_attn_part[2])[i];
    float4 d = ((const float4*)g_attn_part[3])[i];
    float4 o;
    o.x = (a.x + b.x) + (c.x + d.x);
    o.y = (a.y + b.y) + (c.y + d.y);
    o.z = (a.z + b.z) + (c.z + d.z);
    o.w = (a.w + b.w) + (c.w + d.w);
    ((float4*)g_attn)[i] = o;
}

// ---------------- kernel E: project back through w_red -----------------------
__global__ void k_attn_proj(const float* __restrict__ w_red,
                            float* __restrict__ dst)
{
    int b2 = blockIdx.z;
    int s0 = blockIdx.x * 128;
    int c0 = blockIdx.y * 32;
    __shared__ __align__(16) float Os[128][33];   // [s][r]
    __shared__ __align__(16) float Ws[RC][32];    // [r][c]
    int tid = threadIdx.x;   // 256
    #pragma unroll
    for (int idx = tid; idx < 128 * RC; idx += 256) {
        int sr = idx >> 5, r = idx & 31;
        Os[sr][r] = g_attn[(size_t)(b2 * NS + s0 + sr) * RC + r];
    }
    #pragma unroll
    for (int idx = tid; idx < RC * 32; idx += 256) {
        int r = idx >> 5, cc = idx & 31;
        Ws[r][cc] = w_red[r * NC + c0 + cc];
    }
    __syncthreads();
    int sl = tid & 127;
    int cg = (tid >> 7) * 16;
    float4 acc0 = {0,0,0,0}, acc1 = {0,0,0,0}, acc2 = {0,0,0,0}, acc3 = {0,0,0,0};
    #pragma unroll
    for (int r = 0; r < RC; r++) {
        float o = Os[sl][r];
        float4 w0 = *(const float4*)&Ws[r][cg + 0];
        float4 w1 = *(const float4*)&Ws[r][cg + 4];
        float4 w2 = *(const float4*)&Ws[r][cg + 8];
        float4 w3 = *(const float4*)&Ws[r][cg + 12];
        acc0.x += o*w0.x; acc0.y += o*w0.y; acc0.z += o*w0.z; acc0.w += o*w0.w;
        acc1.x += o*w1.x; acc1.y += o*w1.y; acc1.z += o*w1.z; acc1.w += o*w1.w;
        acc2.x += o*w2.x; acc2.y += o*w2.y; acc2.z += o*w2.z; acc2.w += o*w2.w;
        acc3.x += o*w3.x; acc3.y += o*w3.y; acc3.z += o*w3.z; acc3.w += o*w3.w;
    }
    float accs[16] = {acc0.x,acc0.y,acc0.z,acc0.w, acc1.x,acc1.y,acc1.z,acc1.w,
                      acc2.x,acc2.y,acc2.z,acc2.w, acc3.x,acc3.y,acc3.z,acc3.w};
    #pragma unroll
    for (int i = 0; i < 16; i++)
        dst[(size_t)(b2 * NC + c0 + cg + i) * NS + s0 + sl] = accs[i];
}

// ---------------- launcher ---------------------------------------------------
extern "C" void kernel_launch(void* const* d_in, const int* in_sizes, int n_in,
                              void* d_out, int out_size)
{
    const float* x        = (const float*)d_in[0];
    const float* mix      = (const float*)d_in[1];
    const float* w_red    = (const float*)d_in[2];
    const float* b_red    = (const float*)d_in[3];
    const float* w_qkv    = (const float*)d_in[4];
    const float* b_qkv    = (const float*)d_in[5];
    const float* w_s1     = (const float*)d_in[6];
    const float* b_s1     = (const float*)d_in[7];
    const float* w_s2     = (const float*)d_in[8];
    const float* b_s2     = (const float*)d_in[9];
    float* out = (float*)d_out;
    float* out_attn = out + (size_t)NB * NC * NS;   // 524288 offset

    k_pool_combine<<<dim3(NC, NB), 256>>>(x, mix);
    k_fuse_w<<<NJ, 256>>>(w_red, b_red, w_qkv, b_qkv);
    k_gating<<<1, 128>>>(w_s1, b_s1, w_s2, b_s2);
    k_gate_max<<<512, 256>>>(out);
    k_qkv<<<dim3(NS / 64, 3, NB2), 256>>>();
    k_scores<<<dim3(NS / 64, NS / 64, NB2), 256>>>();
    k_vtrans<<<dim3(NS / 64, NB2), 256>>>();
    k_topk_softmax<<<(NB2 * NS) / 8, 256>>>();
    k_attn_av<<<dim3(NS / 64, 4, NB2), 128>>>();
    k_attn_reduce<<<128, 256>>>();
    k_attn_proj<<<dim3(NS / 128, NC / 32, NB2), 256>>>(w_red, out_attn);
}